// round 1
// baseline (speedup 1.0000x reference)
#include <cuda_runtime.h>

#define Nn   100000
#define Ee   800000
#define Dd   384
#define OUTC 2

// ---------------- device scratch (no allocations allowed) ----------------
__device__ float g_mean[(size_t)Nn * Dd];   // 153.6 MB
__device__ float g_h[(size_t)Nn * Dd];      // 153.6 MB
__device__ int   g_deg[Nn];
__device__ int   g_ptr[Nn + 1];
__device__ int   g_cursor[Nn];
__device__ int   g_col[Ee];
__device__ float g_wt[Ee];
__device__ int   g_part[256];
__device__ int   g_is64;

// ---------------- edge_index dtype detection ----------------
// jnp.int64 is silently canonicalized to int32 under default JAX config, so the
// actual dtype is ambiguous. If data is int64 (little-endian, values < 2^32,
// non-negative), every odd int32 word is 0. Random int32 indices in [0,100000)
// make 512 consecutive zeros at odd positions essentially impossible.
__global__ void k_detect(const int* __restrict__ ei) {
    if (blockIdx.x == 0 && threadIdx.x == 0) {
        int is64 = 1;
        for (int i = 0; i < 512; i++) {
            if (ei[2 * i + 1] != 0) { is64 = 0; break; }
        }
        g_is64 = is64;
    }
}

__device__ __forceinline__ int edge_at(const void* ei, int pos) {
    if (g_is64) return (int)((const long long*)ei)[pos];
    return ((const int*)ei)[pos];
}

// ---------------- CSR build ----------------
__global__ void k_zero() {
    int i = blockIdx.x * blockDim.x + threadIdx.x;
    if (i < Nn) g_deg[i] = 0;
}

__global__ void k_count(const void* __restrict__ ei) {
    int e = blockIdx.x * blockDim.x + threadIdx.x;
    if (e < Ee) {
        int d = edge_at(ei, Ee + e);
        atomicAdd(&g_deg[d], 1);
    }
}

// block-wise inclusive scan of g_deg into g_ptr, per-block totals into g_part
__global__ void k_scan1() {
    __shared__ int s[1024];
    int tid = threadIdx.x;
    int i = blockIdx.x * 1024 + tid;
    int v = (i < Nn) ? g_deg[i] : 0;
    s[tid] = v;
    __syncthreads();
    for (int off = 1; off < 1024; off <<= 1) {
        int t = (tid >= off) ? s[tid - off] : 0;
        __syncthreads();
        s[tid] += t;
        __syncthreads();
    }
    if (i < Nn) g_ptr[i] = s[tid];
    if (tid == 1023) g_part[blockIdx.x] = s[1023];
}

__global__ void k_scan2(int nblk) {
    if (threadIdx.x == 0) {
        int run = 0;
        for (int b = 0; b < nblk; b++) {
            int t = g_part[b];
            g_part[b] = run;
            run += t;
        }
    }
}

// finalize: exclusive global offsets; init fill cursors
__global__ void k_scan3() {
    int i = blockIdx.x * blockDim.x + threadIdx.x;
    if (i < Nn) {
        int excl = g_ptr[i] - g_deg[i] + g_part[i >> 10];
        g_ptr[i] = excl;
        g_cursor[i] = excl;
    }
    if (i == 0) g_ptr[Nn] = Ee;
}

__global__ void k_fill(const void* __restrict__ ei, const float* __restrict__ ew) {
    int e = blockIdx.x * blockDim.x + threadIdx.x;
    if (e < Ee) {
        int s = edge_at(ei, e);
        int d = edge_at(ei, Ee + e);
        int pos = atomicAdd(&g_cursor[d], 1);
        g_col[pos] = s;
        g_wt[pos] = ew[e];
    }
}

// ---------------- mean aggregation: warp per destination node ----------------
__global__ void k_agg(const float* __restrict__ xext, int use_h) {
    int gw = (blockIdx.x * blockDim.x + threadIdx.x) >> 5;
    int lane = threadIdx.x & 31;
    if (gw >= Nn) return;
    const float* X = use_h ? g_h : xext;
    int s = g_ptr[gw], eEnd = g_ptr[gw + 1];
    float acc[12];
#pragma unroll
    for (int j = 0; j < 12; j++) acc[j] = 0.f;
    for (int e = s; e < eEnd; e++) {
        int src = g_col[e];
        float w = g_wt[e];
        const float* xr = X + (size_t)src * Dd;
#pragma unroll
        for (int j = 0; j < 12; j++) acc[j] += w * xr[lane + 32 * j];
    }
    float inv = 1.f / fmaxf((float)(eEnd - s), 1.f);
    float* mr = g_mean + (size_t)gw * Dd;
#pragma unroll
    for (int j = 0; j < 12; j++) mr[lane + 32 * j] = acc[j] * inv;
}

// ---------------- fused GraphConv GEMM ----------------
// out = relu(g_mean @ Wrel + A2 @ Wroot + brel)
// layer==1: A2 = x (input),  dest = g_h
// layer==2: A2 = g_h,        dest = yout
// 128x128 tile, BK=8, 256 threads, 8x8 micro-tile per thread.
__global__ __launch_bounds__(256) void k_layer(
    const float* __restrict__ xext,
    const float* __restrict__ Wrel, const float* __restrict__ brel,
    const float* __restrict__ Wroot,
    float* __restrict__ yout, int layer)
{
    __shared__ float As[8 * 128];
    __shared__ float Bs[8 * 128];

    const float* A2 = (layer == 1) ? xext : g_h;
    float* Od = (layer == 1) ? g_h : yout;

    int t = threadIdx.x;
    int tx = t & 15;      // col group 0..15
    int ty = t >> 4;      // row group 0..15
    int rowBase = blockIdx.y * 128;
    int colBase = blockIdx.x * 128;

    float acc[8][8];
#pragma unroll
    for (int i = 0; i < 8; i++)
#pragma unroll
        for (int j = 0; j < 8; j++) acc[i][j] = 0.f;

    int ar = t >> 1;            // 0..127 (A tile row)
    int ac = (t & 1) * 4;       // 0 or 4 (A tile col)
    int br = t >> 5;            // 0..7   (B tile row)
    int bc = (t & 31) * 4;      // 0..124 (B tile col)
    int growA = rowBase + ar;

#pragma unroll 1
    for (int op = 0; op < 2; op++) {
        const float* A = op ? A2 : g_mean;
        const float* W = op ? Wroot : Wrel;
#pragma unroll 1
        for (int k0 = 0; k0 < Dd; k0 += 8) {
            float4 av = make_float4(0.f, 0.f, 0.f, 0.f);
            if (growA < Nn)
                av = *(const float4*)(A + (size_t)growA * Dd + k0 + ac);
            As[(ac + 0) * 128 + ar] = av.x;
            As[(ac + 1) * 128 + ar] = av.y;
            As[(ac + 2) * 128 + ar] = av.z;
            As[(ac + 3) * 128 + ar] = av.w;
            float4 bv = *(const float4*)(W + (size_t)(k0 + br) * Dd + colBase + bc);
            *(float4*)(Bs + br * 128 + bc) = bv;
            __syncthreads();
#pragma unroll
            for (int kk = 0; kk < 8; kk++) {
                float a[8], b[8];
#pragma unroll
                for (int i = 0; i < 8; i++) a[i] = As[kk * 128 + ty * 8 + i];
#pragma unroll
                for (int j = 0; j < 8; j++) b[j] = Bs[kk * 128 + tx * 8 + j];
#pragma unroll
                for (int i = 0; i < 8; i++)
#pragma unroll
                    for (int j = 0; j < 8; j++) acc[i][j] += a[i] * b[j];
            }
            __syncthreads();
        }
    }

    // epilogue: bias + relu
#pragma unroll
    for (int i = 0; i < 8; i++) {
        int grow = rowBase + ty * 8 + i;
        if (grow >= Nn) continue;
#pragma unroll
        for (int j = 0; j < 8; j++) {
            int col = colBase + tx * 8 + j;
            float v = acc[i][j] + brel[col];
            Od[(size_t)grow * Dd + col] = fmaxf(v, 0.f);
        }
    }
}

// ---------------- final linear + sigmoid: warp per node ----------------
__global__ void k_final(const float* __restrict__ y,
                        const float* __restrict__ Wl,
                        const float* __restrict__ bl,
                        float* __restrict__ out)
{
    int gw = (blockIdx.x * blockDim.x + threadIdx.x) >> 5;
    int lane = threadIdx.x & 31;
    if (gw >= Nn) return;
    const float* yr = y + (size_t)gw * Dd;
    float s0 = 0.f, s1 = 0.f;
#pragma unroll
    for (int j = 0; j < 12; j++) {
        int k = lane + 32 * j;
        float v = yr[k];
        s0 += v * Wl[k * 2 + 0];
        s1 += v * Wl[k * 2 + 1];
    }
#pragma unroll
    for (int off = 16; off; off >>= 1) {
        s0 += __shfl_down_sync(0xffffffffu, s0, off);
        s1 += __shfl_down_sync(0xffffffffu, s1, off);
    }
    if (lane == 0) {
        out[gw * 2 + 0] = 1.f / (1.f + expf(-(s0 + bl[0])));
        out[gw * 2 + 1] = 1.f / (1.f + expf(-(s1 + bl[1])));
    }
}

// ---------------- launch ----------------
extern "C" void kernel_launch(void* const* d_in, const int* in_sizes, int n_in,
                              void* d_out, int out_size)
{
    const float* x   = (const float*)d_in[0];
    const void*  ei  = d_in[1];
    const float* ew  = (const float*)d_in[2];
    const float* Wr1 = (const float*)d_in[3];
    const float* br1 = (const float*)d_in[4];
    const float* Wo1 = (const float*)d_in[5];
    const float* Wr2 = (const float*)d_in[6];
    const float* br2 = (const float*)d_in[7];
    const float* Wo2 = (const float*)d_in[8];
    const float* Wl  = (const float*)d_in[9];
    const float* bl  = (const float*)d_in[10];

    float* out = (float*)d_out;                 // [N, 2]   sigmoid output
    float* y   = out + (size_t)Nn * OUTC;       // [N, 384] second relu output

    int nblk = (Nn + 1023) / 1024;

    k_detect<<<1, 32>>>((const int*)ei);
    k_zero<<<(Nn + 255) / 256, 256>>>();
    k_count<<<(Ee + 255) / 256, 256>>>(ei);
    k_scan1<<<nblk, 1024>>>();
    k_scan2<<<1, 32>>>(nblk);
    k_scan3<<<(Nn + 255) / 256, 256>>>();
    k_fill<<<(Ee + 255) / 256, 256>>>(ei, ew);

    // layer 1
    k_agg<<<(Nn * 32 + 255) / 256, 256>>>(x, 0);
    dim3 gg(Dd / 128, (Nn + 127) / 128);
    k_layer<<<gg, 256>>>(x, Wr1, br1, Wo1, nullptr, 1);

    // layer 2
    k_agg<<<(Nn * 32 + 255) / 256, 256>>>(nullptr, 1);
    k_layer<<<gg, 256>>>(nullptr, Wr2, br2, Wo2, y, 2);

    // head
    k_final<<<(Nn * 32 + 255) / 256, 256>>>(y, Wl, bl, out);
}

// round 3
// speedup vs baseline: 2.5294x; 2.5294x over previous
#include <cuda_runtime.h>
#include <cstdint>

#define Nn   100000
#define Ee   800000
#define Dd   384
#define OUTC 2

// ---------------- device scratch (no allocations allowed) ----------------
__device__ float g_mean[(size_t)Nn * Dd];   // 153.6 MB  (stored tf32-rounded)
__device__ float g_h[(size_t)Nn * Dd];      // 153.6 MB
__device__ float g_W[4][Dd * Dd];           // tf32-rounded weights: Wr1,Wo1,Wr2,Wo2
__device__ int   g_deg[Nn];
__device__ int   g_ptr[Nn + 1];
__device__ int   g_cursor[Nn];
__device__ int   g_col[Ee];
__device__ float g_wt[Ee];
__device__ int   g_part[256];
__device__ int   g_is64;

// ---------------- small helpers ----------------
__device__ __forceinline__ uint32_t f2tf(float x) {
    uint32_t r;
    asm("cvt.rna.tf32.f32 %0, %1;\n" : "=r"(r) : "f"(x));
    return r;
}
__device__ __forceinline__ float f2tf_f(float x) { return __uint_as_float(f2tf(x)); }

__device__ __forceinline__ void cp16(void* smem, const void* g, bool pred) {
    uint32_t s = (uint32_t)__cvta_generic_to_shared(smem);
    int bytes = pred ? 16 : 0;
    asm volatile("cp.async.cg.shared.global [%0], [%1], 16, %2;\n"
                 :: "r"(s), "l"(g), "r"(bytes));
}
#define CP_COMMIT() asm volatile("cp.async.commit_group;\n" ::: "memory")
#define CP_WAIT(n)  asm volatile("cp.async.wait_group %0;\n" :: "n"(n) : "memory")

__device__ __forceinline__ void mma_tf32(float* d, const uint32_t* a, const uint32_t* b) {
    asm volatile(
        "mma.sync.aligned.m16n8k8.row.col.f32.tf32.tf32.f32 "
        "{%0,%1,%2,%3}, {%4,%5,%6,%7}, {%8,%9}, {%0,%1,%2,%3};\n"
        : "+f"(d[0]), "+f"(d[1]), "+f"(d[2]), "+f"(d[3])
        : "r"(a[0]), "r"(a[1]), "r"(a[2]), "r"(a[3]), "r"(b[0]), "r"(b[1]));
}

// ---------------- edge_index dtype detection ----------------
// jnp.int64 may be canonicalized to int32 by JAX. If data really is int64
// (little-endian, values < 2^32), every odd int32 word is 0.
__global__ void k_detect(const int* __restrict__ ei) {
    if (blockIdx.x == 0 && threadIdx.x == 0) {
        int is64 = 1;
        for (int i = 0; i < 512; i++)
            if (ei[2 * i + 1] != 0) { is64 = 0; break; }
        g_is64 = is64;
    }
}
__device__ __forceinline__ int edge_at(const void* ei, int pos) {
    if (g_is64) return (int)((const long long*)ei)[pos];
    return ((const int*)ei)[pos];
}

// ---------------- weight pre-rounding (RN to tf32) ----------------
__global__ void k_round_w(const float* __restrict__ w0, const float* __restrict__ w1,
                          const float* __restrict__ w2, const float* __restrict__ w3) {
    int i = blockIdx.x * blockDim.x + threadIdx.x;
    if (i < Dd * Dd) {
        g_W[0][i] = f2tf_f(w0[i]);
        g_W[1][i] = f2tf_f(w1[i]);
        g_W[2][i] = f2tf_f(w2[i]);
        g_W[3][i] = f2tf_f(w3[i]);
    }
}

// ---------------- CSR build ----------------
__global__ void k_zero() {
    int i = blockIdx.x * blockDim.x + threadIdx.x;
    if (i < Nn) g_deg[i] = 0;
}
__global__ void k_count(const void* __restrict__ ei) {
    int e = blockIdx.x * blockDim.x + threadIdx.x;
    if (e < Ee) atomicAdd(&g_deg[edge_at(ei, Ee + e)], 1);
}
__global__ void k_scan1() {
    __shared__ int s[1024];
    int tid = threadIdx.x;
    int i = blockIdx.x * 1024 + tid;
    int v = (i < Nn) ? g_deg[i] : 0;
    s[tid] = v;
    __syncthreads();
    for (int off = 1; off < 1024; off <<= 1) {
        int t = (tid >= off) ? s[tid - off] : 0;
        __syncthreads();
        s[tid] += t;
        __syncthreads();
    }
    if (i < Nn) g_ptr[i] = s[tid];
    if (tid == 1023) g_part[blockIdx.x] = s[1023];
}
__global__ void k_scan2(int nblk) {
    if (threadIdx.x == 0) {
        int run = 0;
        for (int b = 0; b < nblk; b++) { int t = g_part[b]; g_part[b] = run; run += t; }
    }
}
__global__ void k_scan3() {
    int i = blockIdx.x * blockDim.x + threadIdx.x;
    if (i < Nn) {
        int excl = g_ptr[i] - g_deg[i] + g_part[i >> 10];
        g_ptr[i] = excl;
        g_cursor[i] = excl;
    }
    if (i == 0) g_ptr[Nn] = Ee;
}
__global__ void k_fill(const void* __restrict__ ei, const float* __restrict__ ew) {
    int e = blockIdx.x * blockDim.x + threadIdx.x;
    if (e < Ee) {
        int s = edge_at(ei, e);
        int d = edge_at(ei, Ee + e);
        int pos = atomicAdd(&g_cursor[d], 1);
        g_col[pos] = s;
        g_wt[pos] = ew[e];
    }
}

// ---------------- mean aggregation: warp per destination node ----------------
// Stores the mean already RN-rounded to tf32 (its only consumer is the MMA GEMM).
__global__ void k_agg(const float* __restrict__ xext, int use_h) {
    int gw = (blockIdx.x * blockDim.x + threadIdx.x) >> 5;
    int lane = threadIdx.x & 31;
    if (gw >= Nn) return;
    const float4* X = (const float4*)(use_h ? g_h : xext);
    int s = g_ptr[gw], eEnd = g_ptr[gw + 1];
    float4 a0 = make_float4(0.f, 0.f, 0.f, 0.f), a1 = a0, a2 = a0;
    for (int e = s; e < eEnd; e++) {
        int src = g_col[e];
        float w = g_wt[e];
        const float4* xr = X + (size_t)src * (Dd / 4);
        float4 v0 = xr[lane], v1 = xr[lane + 32], v2 = xr[lane + 64];
        a0.x += w * v0.x; a0.y += w * v0.y; a0.z += w * v0.z; a0.w += w * v0.w;
        a1.x += w * v1.x; a1.y += w * v1.y; a1.z += w * v1.z; a1.w += w * v1.w;
        a2.x += w * v2.x; a2.y += w * v2.y; a2.z += w * v2.z; a2.w += w * v2.w;
    }
    float inv = 1.f / fmaxf((float)(eEnd - s), 1.f);
    float4* mr = (float4*)(g_mean + (size_t)gw * Dd);
    float4 r0, r1, r2;
    r0.x = f2tf_f(a0.x * inv); r0.y = f2tf_f(a0.y * inv);
    r0.z = f2tf_f(a0.z * inv); r0.w = f2tf_f(a0.w * inv);
    r1.x = f2tf_f(a1.x * inv); r1.y = f2tf_f(a1.y * inv);
    r1.z = f2tf_f(a1.z * inv); r1.w = f2tf_f(a1.w * inv);
    r2.x = f2tf_f(a2.x * inv); r2.y = f2tf_f(a2.y * inv);
    r2.z = f2tf_f(a2.z * inv); r2.w = f2tf_f(a2.w * inv);
    mr[lane] = r0; mr[lane + 32] = r1; mr[lane + 64] = r2;
}

// ---------------- fused GraphConv GEMM on tensor pipe (TF32 mma.sync) ----------
// Od = relu(g_mean @ Wrel + A2 @ Wroot + brel)
// 128x128 CTA tile, BK=32, 8 warps (32x64 warp tiles), cp.async double buffer.
#define BM 128
#define BN 128
#define BK 32
#define AS_STRIDE 36    // floats; (lq*36+lr) % 32 = lq*4+lr -> conflict-free
#define BS_STRIDE 132   // floats; (lr*132+lq) % 32 = lr*4+lq -> conflict-free
#define ASZ (BM * AS_STRIDE)   // 4608 floats
#define BSZ (BK * BS_STRIDE)   // 4224 floats
#define SMEM_BYTES (2 * (ASZ + BSZ) * 4)  // 70656

__global__ __launch_bounds__(256) void k_layer_mma(
    const float* __restrict__ xext,
    const float* __restrict__ Wrel, const float* __restrict__ brel,
    const float* __restrict__ Wroot,
    float* __restrict__ yout, int layer)
{
    extern __shared__ float sm[];
    float* const AsP[2] = { sm, sm + ASZ + BSZ };
    float* const BsP[2] = { sm + ASZ, sm + 2 * ASZ + BSZ };

    const float* A2 = (layer == 1) ? xext : g_h;
    float* Od = (layer == 1) ? g_h : yout;

    const int t = threadIdx.x;
    const int warp = t >> 5, lane = t & 31;
    const int warpM = warp >> 1, warpN = warp & 1;
    const int lq = lane >> 2, lr = lane & 3;
    const int rowBase = blockIdx.y * BM;
    const int colBase = blockIdx.x * BN;

    float acc[2][8][4];
#pragma unroll
    for (int mm = 0; mm < 2; mm++)
#pragma unroll
        for (int nn = 0; nn < 8; nn++)
#pragma unroll
            for (int q = 0; q < 4; q++) acc[mm][nn][q] = 0.f;

    // staging indices
    const int a_row = t >> 3;     // 0..31 (+i*32)
    const int a_c4 = (t & 7) * 4; // k offset in floats
    const int b_k = t >> 5;       // 0..7 (+i*8)
    const int b_n4 = (t & 31) * 4;

    // 24 K-iterations: it<12 -> (g_mean, Wrel); it>=12 -> (A2, Wroot)
    auto stage = [&](int it, int buf) {
        const float* A = (it < 12) ? g_mean : A2;
        const float* W = (it < 12) ? Wrel : Wroot;
        int k0 = (it < 12 ? it : it - 12) * BK;
        float* As = AsP[buf];
        float* Bs = BsP[buf];
#pragma unroll
        for (int i = 0; i < 4; i++) {
            int r = a_row + i * 32;
            int grow = rowBase + r;
            cp16(&As[r * AS_STRIDE + a_c4],
                 A + (size_t)grow * Dd + k0 + a_c4, grow < Nn);
        }
#pragma unroll
        for (int i = 0; i < 4; i++) {
            int k = b_k + i * 8;
            cp16(&Bs[k * BS_STRIDE + b_n4],
                 W + (size_t)(k0 + k) * Dd + colBase + b_n4, true);
        }
    };

    auto compute = [&](int buf, bool cvtA) {
        const float* As = AsP[buf];
        const float* Bs = BsP[buf];
#pragma unroll
        for (int ks = 0; ks < 4; ks++) {
            const int kb = ks * 8;
            uint32_t af[2][4], bf[8][2];
#pragma unroll
            for (int mm = 0; mm < 2; mm++) {
                const float* base = &As[(warpM * 32 + mm * 16 + lq) * AS_STRIDE + kb + lr];
                float v0 = base[0];
                float v1 = base[8 * AS_STRIDE];
                float v2 = base[4];
                float v3 = base[8 * AS_STRIDE + 4];
                if (cvtA) {
                    af[mm][0] = f2tf(v0); af[mm][1] = f2tf(v1);
                    af[mm][2] = f2tf(v2); af[mm][3] = f2tf(v3);
                } else {
                    af[mm][0] = __float_as_uint(v0); af[mm][1] = __float_as_uint(v1);
                    af[mm][2] = __float_as_uint(v2); af[mm][3] = __float_as_uint(v3);
                }
            }
#pragma unroll
            for (int nn = 0; nn < 8; nn++) {
                const float* base = &Bs[(kb + lr) * BS_STRIDE + warpN * 64 + nn * 8 + lq];
                bf[nn][0] = __float_as_uint(base[0]);               // weights pre-rounded
                bf[nn][1] = __float_as_uint(base[4 * BS_STRIDE]);
            }
#pragma unroll
            for (int mm = 0; mm < 2; mm++)
#pragma unroll
                for (int nn = 0; nn < 8; nn++)
                    mma_tf32(acc[mm][nn], af[mm], bf[nn]);
        }
    };

    stage(0, 0); CP_COMMIT();
    stage(1, 1); CP_COMMIT();
    int buf = 0;
#pragma unroll 1
    for (int it = 0; it < 24; it++) {
        if (it < 23) { CP_WAIT(1); } else { CP_WAIT(0); }
        __syncthreads();
        compute(buf, it >= 12);
        __syncthreads();
        if (it + 2 < 24) { stage(it + 2, buf); CP_COMMIT(); }
        buf ^= 1;
    }

    // epilogue: bias + relu, float2 stores
#pragma unroll
    for (int mm = 0; mm < 2; mm++) {
#pragma unroll
        for (int nn = 0; nn < 8; nn++) {
            int c = colBase + warpN * 64 + nn * 8 + lr * 2;
            float b0 = brel[c], b1 = brel[c + 1];
            int r0 = rowBase + warpM * 32 + mm * 16 + lq;
            if (r0 < Nn) {
                float2 v = make_float2(fmaxf(acc[mm][nn][0] + b0, 0.f),
                                       fmaxf(acc[mm][nn][1] + b1, 0.f));
                *(float2*)(Od + (size_t)r0 * Dd + c) = v;
            }
            int r1 = r0 + 8;
            if (r1 < Nn) {
                float2 v = make_float2(fmaxf(acc[mm][nn][2] + b0, 0.f),
                                       fmaxf(acc[mm][nn][3] + b1, 0.f));
                *(float2*)(Od + (size_t)r1 * Dd + c) = v;
            }
        }
    }
}

// ---------------- final linear + sigmoid: warp per node ----------------
__global__ void k_final(const float* __restrict__ y,
                        const float* __restrict__ Wl,
                        const float* __restrict__ bl,
                        float* __restrict__ out)
{
    int gw = (blockIdx.x * blockDim.x + threadIdx.x) >> 5;
    int lane = threadIdx.x & 31;
    if (gw >= Nn) return;
    const float* yr = y + (size_t)gw * Dd;
    float s0 = 0.f, s1 = 0.f;
#pragma unroll
    for (int j = 0; j < 12; j++) {
        int k = lane + 32 * j;
        float v = yr[k];
        s0 += v * Wl[k * 2 + 0];
        s1 += v * Wl[k * 2 + 1];
    }
#pragma unroll
    for (int off = 16; off; off >>= 1) {
        s0 += __shfl_down_sync(0xffffffffu, s0, off);
        s1 += __shfl_down_sync(0xffffffffu, s1, off);
    }
    if (lane == 0) {
        out[gw * 2 + 0] = 1.f / (1.f + expf(-(s0 + bl[0])));
        out[gw * 2 + 1] = 1.f / (1.f + expf(-(s1 + bl[1])));
    }
}

// ---------------- launch ----------------
extern "C" void kernel_launch(void* const* d_in, const int* in_sizes, int n_in,
                              void* d_out, int out_size)
{
    const float* x   = (const float*)d_in[0];
    const void*  ei  = d_in[1];
    const float* ew  = (const float*)d_in[2];
    const float* Wr1 = (const float*)d_in[3];
    const float* br1 = (const float*)d_in[4];
    const float* Wo1 = (const float*)d_in[5];
    const float* Wr2 = (const float*)d_in[6];
    const float* br2 = (const float*)d_in[7];
    const float* Wo2 = (const float*)d_in[8];
    const float* Wl  = (const float*)d_in[9];
    const float* bl  = (const float*)d_in[10];

    float* out = (float*)d_out;                 // [N, 2]
    float* y   = out + (size_t)Nn * OUTC;       // [N, 384]

    (void)cudaFuncSetAttribute(k_layer_mma,
                               cudaFuncAttributeMaxDynamicSharedMemorySize,
                               SMEM_BYTES);

    int nblk = (Nn + 1023) / 1024;

    k_detect<<<1, 32>>>((const int*)ei);
    k_round_w<<<(Dd * Dd + 255) / 256, 256>>>(Wr1, Wo1, Wr2, Wo2);
    k_zero<<<(Nn + 255) / 256, 256>>>();
    k_count<<<(Ee + 255) / 256, 256>>>(ei);
    k_scan1<<<nblk, 1024>>>();
    k_scan2<<<1, 32>>>(nblk);
    k_scan3<<<(Nn + 255) / 256, 256>>>();
    k_fill<<<(Ee + 255) / 256, 256>>>(ei, ew);

    // device pointers to pre-rounded weights
    float* gW;
    cudaGetSymbolAddress((void**)&gW, g_W);
    const float* Wr1t = gW;
    const float* Wo1t = gW + 1 * Dd * Dd;
    const float* Wr2t = gW + 2 * Dd * Dd;
    const float* Wo2t = gW + 3 * Dd * Dd;

    dim3 gg(Dd / BN, (Nn + BM - 1) / BM);  // (3, 782)

    // layer 1
    k_agg<<<(Nn * 32 + 255) / 256, 256>>>(x, 0);
    k_layer_mma<<<gg, 256, SMEM_BYTES>>>(x, Wr1t, br1, Wo1t, nullptr, 1);

    // layer 2
    k_agg<<<(Nn * 32 + 255) / 256, 256>>>(nullptr, 1);
    k_layer_mma<<<gg, 256, SMEM_BYTES>>>(nullptr, Wr2t, br2, Wo2t, y, 2);

    // head
    k_final<<<(Nn * 32 + 255) / 256, 256>>>(y, Wl, bl, out);
}

// round 4
// speedup vs baseline: 2.8210x; 1.1153x over previous
#include <cuda_runtime.h>
#include <cuda_fp16.h>
#include <cstdint>

#define Nn   100000
#define Ee   800000
#define Dd   384
#define OUTC 2

// ---------------- device scratch (no allocations allowed) ----------------
__device__ __half g_xh[(size_t)Nn * Dd];    // 76.8 MB  fp16 copy of x
__device__ __half g_meanh[(size_t)Nn * Dd]; // 76.8 MB  aggregated mean (fp16)
__device__ __half g_hh[(size_t)Nn * Dd];    // 76.8 MB  layer-1 output (fp16)
__device__ float  g_W[4][Dd * Dd];          // tf32-rounded weights
__device__ int    g_deg[Nn];
__device__ int    g_ptr[Nn + 1];
__device__ int    g_cursor[Nn];
__device__ int    g_col[Ee];
__device__ float  g_wt[Ee];
__device__ int    g_part[128];
__device__ int    g_is64;

// ---------------- small helpers ----------------
__device__ __forceinline__ float f2tf_f(float x) {
    uint32_t r;
    asm("cvt.rna.tf32.f32 %0, %1;\n" : "=r"(r) : "f"(x));
    return __uint_as_float(r);
}

__device__ __forceinline__ void cp16(void* smem, const void* g, bool pred) {
    uint32_t s = (uint32_t)__cvta_generic_to_shared(smem);
    int bytes = pred ? 16 : 0;
    asm volatile("cp.async.cg.shared.global [%0], [%1], 16, %2;\n"
                 :: "r"(s), "l"(g), "r"(bytes));
}
#define CP_COMMIT() asm volatile("cp.async.commit_group;\n" ::: "memory")
#define CP_WAIT(n)  asm volatile("cp.async.wait_group %0;\n" :: "n"(n) : "memory")

__device__ __forceinline__ void mma_tf32(float* d, const uint32_t* a, const uint32_t* b) {
    asm volatile(
        "mma.sync.aligned.m16n8k8.row.col.f32.tf32.tf32.f32 "
        "{%0,%1,%2,%3}, {%4,%5,%6,%7}, {%8,%9}, {%0,%1,%2,%3};\n"
        : "+f"(d[0]), "+f"(d[1]), "+f"(d[2]), "+f"(d[3])
        : "r"(a[0]), "r"(a[1]), "r"(a[2]), "r"(a[3]), "r"(b[0]), "r"(b[1]));
}

__device__ __forceinline__ int edge_at(const void* ei, int pos) {
    if (g_is64) return (int)((const long long*)ei)[pos];
    return ((const int*)ei)[pos];
}

// ---------------- init: dtype-detect + zero deg + round weights + x->fp16 ----
// 37500 blocks x 1024 threads = exactly Nn*Dd threads.
__global__ void k_init(const int* __restrict__ ei,
                       const float* __restrict__ x,
                       const float* __restrict__ w0, const float* __restrict__ w1,
                       const float* __restrict__ w2, const float* __restrict__ w3) {
    size_t i = (size_t)blockIdx.x * blockDim.x + threadIdx.x;
    if (i == 0) {
        // jnp.int64 may be canonicalized to int32 by JAX. If data really is
        // int64 (LE, values < 2^32), every odd int32 word is 0.
        int is64 = 1;
        for (int j = 0; j < 512; j++)
            if (ei[2 * j + 1] != 0) { is64 = 0; break; }
        g_is64 = is64;
    }
    if (i < Nn) g_deg[i] = 0;
    if (i < Dd * Dd) {
        g_W[0][i] = f2tf_f(w0[i]);
        g_W[1][i] = f2tf_f(w1[i]);
        g_W[2][i] = f2tf_f(w2[i]);
        g_W[3][i] = f2tf_f(w3[i]);
    }
    g_xh[i] = __float2half_rn(x[i]);
}

// ---------------- CSR build ----------------
__global__ void k_count(const void* __restrict__ ei) {
    int e = blockIdx.x * blockDim.x + threadIdx.x;
    if (e < Ee) atomicAdd(&g_deg[edge_at(ei, Ee + e)], 1);
}
__global__ void k_scan1() {
    __shared__ int s[1024];
    int tid = threadIdx.x;
    int i = blockIdx.x * 1024 + tid;
    int v = (i < Nn) ? g_deg[i] : 0;
    s[tid] = v;
    __syncthreads();
    for (int off = 1; off < 1024; off <<= 1) {
        int t = (tid >= off) ? s[tid - off] : 0;
        __syncthreads();
        s[tid] += t;
        __syncthreads();
    }
    if (i < Nn) g_ptr[i] = s[tid];
    if (tid == 1023) g_part[blockIdx.x] = s[1023];
}
// merged scan2+scan3: per-thread block-prefix over g_part (<=98 iters, broadcast)
__global__ void k_scan23() {
    int i = blockIdx.x * blockDim.x + threadIdx.x;
    if (i < Nn) {
        int nb = i >> 10;
        int run = 0;
        for (int b = 0; b < nb; b++) run += g_part[b];
        int excl = g_ptr[i] - g_deg[i] + run;
        g_ptr[i] = excl;
        g_cursor[i] = excl;
    }
    if (i == 0) g_ptr[Nn] = Ee;
}
__global__ void k_fill(const void* __restrict__ ei, const float* __restrict__ ew) {
    int e = blockIdx.x * blockDim.x + threadIdx.x;
    if (e < Ee) {
        int s = edge_at(ei, e);
        int d = edge_at(ei, Ee + e);
        int pos = atomicAdd(&g_cursor[d], 1);
        g_col[pos] = s;
        g_wt[pos] = ew[e];
    }
}

// ---------------- mean aggregation: warp per dst node, fp16 rows ----------
// Gathers fp16 rows (uint2 = 4 halves per lane), accumulates fp32,
// writes mean back as fp16 (fp16 mantissa == tf32 mantissa: no extra GEMM error).
__global__ void k_agg(int layer) {
    int gw = (blockIdx.x * blockDim.x + threadIdx.x) >> 5;
    int lane = threadIdx.x & 31;
    if (gw >= Nn) return;
    const uint2* X = (const uint2*)(layer == 1 ? g_xh : g_hh);  // 96 uint2 per row
    int s = g_ptr[gw], eEnd = g_ptr[gw + 1];
    float4 a0 = make_float4(0.f, 0.f, 0.f, 0.f), a1 = a0, a2 = a0;
    for (int e = s; e < eEnd; e++) {
        int src = g_col[e];
        float w = g_wt[e];
        const uint2* xr = X + (size_t)src * (Dd / 4);
        uint2 u0 = __ldg(xr + lane), u1 = __ldg(xr + lane + 32), u2 = __ldg(xr + lane + 64);
        float2 f;
        f = __half22float2(*(__half2*)&u0.x); a0.x += w * f.x; a0.y += w * f.y;
        f = __half22float2(*(__half2*)&u0.y); a0.z += w * f.x; a0.w += w * f.y;
        f = __half22float2(*(__half2*)&u1.x); a1.x += w * f.x; a1.y += w * f.y;
        f = __half22float2(*(__half2*)&u1.y); a1.z += w * f.x; a1.w += w * f.y;
        f = __half22float2(*(__half2*)&u2.x); a2.x += w * f.x; a2.y += w * f.y;
        f = __half22float2(*(__half2*)&u2.y); a2.z += w * f.x; a2.w += w * f.y;
    }
    float inv = 1.f / fmaxf((float)(eEnd - s), 1.f);
    uint2* mr = (uint2*)(g_meanh + (size_t)gw * Dd);
    uint2 o;
    __half2 h;
    h = __floats2half2_rn(a0.x * inv, a0.y * inv); o.x = *(uint32_t*)&h;
    h = __floats2half2_rn(a0.z * inv, a0.w * inv); o.y = *(uint32_t*)&h;
    mr[lane] = o;
    h = __floats2half2_rn(a1.x * inv, a1.y * inv); o.x = *(uint32_t*)&h;
    h = __floats2half2_rn(a1.z * inv, a1.w * inv); o.y = *(uint32_t*)&h;
    mr[lane + 32] = o;
    h = __floats2half2_rn(a2.x * inv, a2.y * inv); o.x = *(uint32_t*)&h;
    h = __floats2half2_rn(a2.z * inv, a2.w * inv); o.y = *(uint32_t*)&h;
    mr[lane + 64] = o;
}

// ---------------- fused GraphConv GEMM (TF32 mma.sync, fp16 A operands) ----
// Od = relu(mean @ Wrel + A2 @ Wroot + brel)
// 128x128 CTA tile, BK=32, 8 warps, cp.async double buffer.
// A in fp16 (exact as tf32); B (weights) pre-rounded tf32 in fp32.
#define BM 128
#define BN 128
#define BK 32
#define ASH 40          // halves; ((lq*40+lr)>>1)%32 -> 16 distinct words, no conflict
#define BS_STRIDE 132   // floats; (lr*132+lq)%32 = lr*4+lq -> conflict-free
#define ABYTES (BM * ASH * 2)              // 10240
#define BBYTES (BK * BS_STRIDE * 4)        // 16896
#define BUFBYTES (ABYTES + BBYTES)         // 27136
#define SMEM_BYTES (2 * BUFBYTES)          // 54272

__global__ __launch_bounds__(256) void k_layer_mma(
    const float* __restrict__ Wrel, const float* __restrict__ brel,
    const float* __restrict__ Wroot,
    float* __restrict__ yout, int layer)
{
    extern __shared__ char sm[];

    const __half* A2 = (layer == 1) ? g_xh : g_hh;
    const int t = threadIdx.x;
    const int warp = t >> 5, lane = t & 31;
    const int warpM = warp >> 1, warpN = warp & 1;
    const int lq = lane >> 2, lr = lane & 3;
    const int rowBase = blockIdx.y * BM;
    const int colBase = blockIdx.x * BN;

    float acc[2][8][4];
#pragma unroll
    for (int mm = 0; mm < 2; mm++)
#pragma unroll
        for (int nn = 0; nn < 8; nn++)
#pragma unroll
            for (int q = 0; q < 4; q++) acc[mm][nn][q] = 0.f;

    const int b_k = t >> 5;
    const int b_n4 = (t & 31) * 4;

    // 24 K-iterations: it<12 -> (g_meanh, Wrel); it>=12 -> (A2, Wroot)
    auto stage = [&](int it, int buf) {
        const __half* A = (it < 12) ? g_meanh : A2;
        const float* W = (it < 12) ? Wrel : Wroot;
        int k0 = (it < 12 ? it : it - 12) * BK;
        __half* As = (__half*)(sm + buf * BUFBYTES);
        float* Bs = (float*)(sm + buf * BUFBYTES + ABYTES);
#pragma unroll
        for (int i = 0; i < 2; i++) {
            int cc = t + i * 256;          // 512 chunks: row = cc>>2, 8-half offset
            int r = cc >> 2;
            int o8 = (cc & 3) * 8;
            int grow = rowBase + r;
            cp16(As + r * ASH + o8, A + (size_t)grow * Dd + k0 + o8, grow < Nn);
        }
#pragma unroll
        for (int i = 0; i < 4; i++) {
            int k = b_k + i * 8;
            cp16(Bs + k * BS_STRIDE + b_n4,
                 W + (size_t)(k0 + k) * Dd + colBase + b_n4, true);
        }
    };

    auto compute = [&](int buf) {
        const __half* As = (const __half*)(sm + buf * BUFBYTES);
        const float* Bs = (const float*)(sm + buf * BUFBYTES + ABYTES);
#pragma unroll
        for (int ks = 0; ks < 4; ks++) {
            const int kb = ks * 8;
            uint32_t af[2][4], bf[8][2];
#pragma unroll
            for (int mm = 0; mm < 2; mm++) {
                const __half* base = &As[(warpM * 32 + mm * 16 + lq) * ASH + kb + lr];
                // fp16 -> fp32 is exact; low mantissa bits zero => valid tf32.
                af[mm][0] = __float_as_uint(__half2float(base[0]));
                af[mm][1] = __float_as_uint(__half2float(base[8 * ASH]));
                af[mm][2] = __float_as_uint(__half2float(base[4]));
                af[mm][3] = __float_as_uint(__half2float(base[8 * ASH + 4]));
            }
#pragma unroll
            for (int nn = 0; nn < 8; nn++) {
                const float* base = &Bs[(kb + lr) * BS_STRIDE + warpN * 64 + nn * 8 + lq];
                bf[nn][0] = __float_as_uint(base[0]);
                bf[nn][1] = __float_as_uint(base[4 * BS_STRIDE]);
            }
#pragma unroll
            for (int mm = 0; mm < 2; mm++)
#pragma unroll
                for (int nn = 0; nn < 8; nn++)
                    mma_tf32(acc[mm][nn], af[mm], bf[nn]);
        }
    };

    stage(0, 0); CP_COMMIT();
    stage(1, 1); CP_COMMIT();
    int buf = 0;
#pragma unroll 1
    for (int it = 0; it < 24; it++) {
        if (it < 23) { CP_WAIT(1); } else { CP_WAIT(0); }
        __syncthreads();
        compute(buf);
        __syncthreads();
        if (it + 2 < 24) { stage(it + 2, buf); CP_COMMIT(); }
        buf ^= 1;
    }

    // epilogue: bias + relu. layer1 -> g_hh (fp16); layer2 -> yout (fp32)
#pragma unroll
    for (int mm = 0; mm < 2; mm++) {
#pragma unroll
        for (int nn = 0; nn < 8; nn++) {
            int c = colBase + warpN * 64 + nn * 8 + lr * 2;
            float b0 = brel[c], b1 = brel[c + 1];
            int r0 = rowBase + warpM * 32 + mm * 16 + lq;
            int r1 = r0 + 8;
            float v00 = fmaxf(acc[mm][nn][0] + b0, 0.f);
            float v01 = fmaxf(acc[mm][nn][1] + b1, 0.f);
            float v10 = fmaxf(acc[mm][nn][2] + b0, 0.f);
            float v11 = fmaxf(acc[mm][nn][3] + b1, 0.f);
            if (layer == 1) {
                if (r0 < Nn) {
                    __half2 h = __floats2half2_rn(v00, v01);
                    *(__half2*)(g_hh + (size_t)r0 * Dd + c) = h;
                }
                if (r1 < Nn) {
                    __half2 h = __floats2half2_rn(v10, v11);
                    *(__half2*)(g_hh + (size_t)r1 * Dd + c) = h;
                }
            } else {
                if (r0 < Nn) *(float2*)(yout + (size_t)r0 * Dd + c) = make_float2(v00, v01);
                if (r1 < Nn) *(float2*)(yout + (size_t)r1 * Dd + c) = make_float2(v10, v11);
            }
        }
    }
}

// ---------------- final linear + sigmoid: warp per node ----------------
__global__ void k_final(const float* __restrict__ y,
                        const float* __restrict__ Wl,
                        const float* __restrict__ bl,
                        float* __restrict__ out)
{
    int gw = (blockIdx.x * blockDim.x + threadIdx.x) >> 5;
    int lane = threadIdx.x & 31;
    if (gw >= Nn) return;
    const float* yr = y + (size_t)gw * Dd;
    float s0 = 0.f, s1 = 0.f;
#pragma unroll
    for (int j = 0; j < 12; j++) {
        int k = lane + 32 * j;
        float v = yr[k];
        s0 += v * Wl[k * 2 + 0];
        s1 += v * Wl[k * 2 + 1];
    }
#pragma unroll
    for (int off = 16; off; off >>= 1) {
        s0 += __shfl_down_sync(0xffffffffu, s0, off);
        s1 += __shfl_down_sync(0xffffffffu, s1, off);
    }
    if (lane == 0) {
        out[gw * 2 + 0] = 1.f / (1.f + expf(-(s0 + bl[0])));
        out[gw * 2 + 1] = 1.f / (1.f + expf(-(s1 + bl[1])));
    }
}

// ---------------- launch ----------------
extern "C" void kernel_launch(void* const* d_in, const int* in_sizes, int n_in,
                              void* d_out, int out_size)
{
    const float* x   = (const float*)d_in[0];
    const void*  ei  = d_in[1];
    const float* ew  = (const float*)d_in[2];
    const float* Wl  = (const float*)d_in[9];
    const float* bl  = (const float*)d_in[10];
    const float* br1 = (const float*)d_in[4];
    const float* br2 = (const float*)d_in[7];

    float* out = (float*)d_out;                 // [N, 2]
    float* y   = out + (size_t)Nn * OUTC;       // [N, 384]

    (void)cudaFuncSetAttribute(k_layer_mma,
                               cudaFuncAttributeMaxDynamicSharedMemorySize,
                               SMEM_BYTES);

    float* gW;
    cudaGetSymbolAddress((void**)&gW, g_W);
    const float* Wr1t = gW;
    const float* Wo1t = gW + 1 * Dd * Dd;
    const float* Wr2t = gW + 2 * Dd * Dd;
    const float* Wo2t = gW + 3 * Dd * Dd;

    dim3 gg(Dd / BN, (Nn + BM - 1) / BM);  // (3, 782)

    // launch order chosen so ncu (-s 5 -c 1) profiles #6 = k_agg(layer 1)
    k_init<<<37500, 1024>>>((const int*)ei, x,
                            (const float*)d_in[3], (const float*)d_in[5],
                            (const float*)d_in[6], (const float*)d_in[8]);   // 1
    k_count<<<(Ee + 255) / 256, 256>>>(ei);                                   // 2
    k_scan1<<<(Nn + 1023) / 1024, 1024>>>();                                  // 3
    k_scan23<<<(Nn + 255) / 256, 256>>>();                                    // 4
    k_fill<<<(Ee + 255) / 256, 256>>>(ei, ew);                                // 5

    k_agg<<<(Nn * 32 + 255) / 256, 256>>>(1);                                 // 6 (profiled)
    k_layer_mma<<<gg, 256, SMEM_BYTES>>>(Wr1t, br1, Wo1t, nullptr, 1);        // 7
    k_agg<<<(Nn * 32 + 255) / 256, 256>>>(2);                                 // 8
    k_layer_mma<<<gg, 256, SMEM_BYTES>>>(Wr2t, br2, Wo2t, y, 2);              // 9
    k_final<<<(Nn * 32 + 255) / 256, 256>>>(y, Wl, bl, out);                  // 10
}

// round 5
// speedup vs baseline: 3.8001x; 1.3471x over previous
#include <cuda_runtime.h>
#include <cuda_fp16.h>
#include <cstdint>

#define Nn   100000
#define Ee   800000
#define Dd   384
#define OUTC 2

// ---------------- device scratch (no allocations allowed) ----------------
__device__ __half g_xh[(size_t)Nn * Dd];    // 76.8 MB  fp16 copy of x
__device__ __half g_meanh[(size_t)Nn * Dd]; // 76.8 MB  aggregated mean (fp16)
__device__ __half g_hh[(size_t)Nn * Dd];    // 76.8 MB  layer-1 output (fp16)
__device__ __half g_Wh[4][Dd * Dd];         // fp16 weights, TRANSPOSED [N][K]
__device__ int    g_deg[Nn];                // zero at load; re-zeroed by k_scan23
__device__ int    g_ptr[Nn + 1];
__device__ int    g_cursor[Nn];
__device__ int    g_col[Ee];
__device__ float  g_wt[Ee];
__device__ int    g_part[128];

// ---------------- helpers ----------------
__device__ __forceinline__ void cp16(void* smem, const void* g, bool pred) {
    uint32_t s = (uint32_t)__cvta_generic_to_shared(smem);
    int bytes = pred ? 16 : 0;
    asm volatile("cp.async.cg.shared.global [%0], [%1], 16, %2;\n"
                 :: "r"(s), "l"(g), "r"(bytes));
}
#define CP_COMMIT() asm volatile("cp.async.commit_group;\n" ::: "memory")
#define CP_WAIT(n)  asm volatile("cp.async.wait_group %0;\n" :: "n"(n) : "memory")

__device__ __forceinline__ void mma_f16(float* d, const uint32_t* a, const uint32_t* b) {
    asm volatile(
        "mma.sync.aligned.m16n8k16.row.col.f32.f16.f16.f32 "
        "{%0,%1,%2,%3}, {%4,%5,%6,%7}, {%8,%9}, {%0,%1,%2,%3};\n"
        : "+f"(d[0]), "+f"(d[1]), "+f"(d[2]), "+f"(d[3])
        : "r"(a[0]), "r"(a[1]), "r"(a[2]), "r"(a[3]), "r"(b[0]), "r"(b[1]));
}

// jnp.int64 may be canonicalized to int32 by JAX. If the data really is int64
// (LE, values < 2^32), every odd int32 word is 0. 16 probes of real random
// indices in [0,100000) being all-zero is impossible. Per-thread (uniform,
// broadcast-cached) to avoid any cross-block ordering on a global flag.
__device__ __forceinline__ bool probe64(const int* __restrict__ ei) {
    bool is64 = true;
#pragma unroll
    for (int j = 1; j < 32; j += 2) is64 &= (ei[j] == 0);
    return is64;
}
__device__ __forceinline__ int edge_at(const void* ei, int pos, bool is64) {
    return is64 ? (int)((const long long*)ei)[pos] : ((const int*)ei)[pos];
}

// ---------------- init: x->fp16, weights->fp16 transposed, degree count -----
// g_deg is zero at module load and re-zeroed by k_scan23 after each use, so
// counting can start immediately (invariant holds on every run).
__global__ void k_init(const int* __restrict__ ei,
                       const float* __restrict__ x,
                       const float* __restrict__ w0, const float* __restrict__ w1,
                       const float* __restrict__ w2, const float* __restrict__ w3) {
    size_t i = (size_t)blockIdx.x * blockDim.x + threadIdx.x;
    g_xh[i] = __float2half_rn(x[i]);
    if (i < Dd * Dd) {
        // transpose: source [K][N] row-major -> dest [N][K]
        int k = (int)i / Dd, n = (int)i % Dd;
        int o = n * Dd + k;
        g_Wh[0][o] = __float2half_rn(w0[i]);
        g_Wh[1][o] = __float2half_rn(w1[i]);
        g_Wh[2][o] = __float2half_rn(w2[i]);
        g_Wh[3][o] = __float2half_rn(w3[i]);
    }
    if (i < Ee) {
        bool is64 = probe64(ei);
        atomicAdd(&g_deg[edge_at(ei, Ee + (int)i, is64)], 1);
    }
}

// ---------------- CSR scan ----------------
__global__ void k_scan1() {
    __shared__ int s[1024];
    int tid = threadIdx.x;
    int i = blockIdx.x * 1024 + tid;
    int v = (i < Nn) ? g_deg[i] : 0;
    s[tid] = v;
    __syncthreads();
    for (int off = 1; off < 1024; off <<= 1) {
        int t = (tid >= off) ? s[tid - off] : 0;
        __syncthreads();
        s[tid] += t;
        __syncthreads();
    }
    if (i < Nn) g_ptr[i] = s[tid];
    if (tid == 1023) g_part[blockIdx.x] = s[1023];
}
// finalize offsets + cursors, then reset g_deg for the next run
__global__ void k_scan23() {
    int i = blockIdx.x * blockDim.x + threadIdx.x;
    if (i < Nn) {
        int nb = i >> 10;
        int run = 0;
        for (int b = 0; b < nb; b++) run += g_part[b];
        int excl = g_ptr[i] - g_deg[i] + run;
        g_ptr[i] = excl;
        g_cursor[i] = excl;
        g_deg[i] = 0;                 // invariant: deg zeroed after consumption
    }
    if (i == 0) g_ptr[Nn] = Ee;
}
__global__ void k_fill(const void* __restrict__ ei, const float* __restrict__ ew) {
    int e = blockIdx.x * blockDim.x + threadIdx.x;
    if (e < Ee) {
        bool is64 = probe64((const int*)ei);
        int s = edge_at(ei, e, is64);
        int d = edge_at(ei, Ee + e, is64);
        int pos = atomicAdd(&g_cursor[d], 1);
        g_col[pos] = s;
        g_wt[pos] = ew[e];
    }
}

// ---------------- mean aggregation: warp per dst node, fp16 rows ----------
__global__ void k_agg(int layer) {
    int gw = (blockIdx.x * blockDim.x + threadIdx.x) >> 5;
    int lane = threadIdx.x & 31;
    if (gw >= Nn) return;
    const uint2* X = (const uint2*)(layer == 1 ? g_xh : g_hh);
    int s = g_ptr[gw], eEnd = g_ptr[gw + 1];
    float4 a0 = make_float4(0.f, 0.f, 0.f, 0.f), a1 = a0, a2 = a0;
    int src = (s < eEnd) ? g_col[s] : 0;
    float w = (s < eEnd) ? g_wt[s] : 0.f;
    for (int e = s; e < eEnd; e++) {
        int nsrc = 0; float nw = 0.f;
        if (e + 1 < eEnd) { nsrc = g_col[e + 1]; nw = g_wt[e + 1]; }
        const uint2* xr = X + (size_t)src * (Dd / 4);
        uint2 u0 = __ldg(xr + lane), u1 = __ldg(xr + lane + 32), u2 = __ldg(xr + lane + 64);
        float2 f;
        f = __half22float2(*(__half2*)&u0.x); a0.x += w * f.x; a0.y += w * f.y;
        f = __half22float2(*(__half2*)&u0.y); a0.z += w * f.x; a0.w += w * f.y;
        f = __half22float2(*(__half2*)&u1.x); a1.x += w * f.x; a1.y += w * f.y;
        f = __half22float2(*(__half2*)&u1.y); a1.z += w * f.x; a1.w += w * f.y;
        f = __half22float2(*(__half2*)&u2.x); a2.x += w * f.x; a2.y += w * f.y;
        f = __half22float2(*(__half2*)&u2.y); a2.z += w * f.x; a2.w += w * f.y;
        src = nsrc; w = nw;
    }
    float inv = 1.f / fmaxf((float)(eEnd - s), 1.f);
    uint2* mr = (uint2*)(g_meanh + (size_t)gw * Dd);
    uint2 o; __half2 h;
    h = __floats2half2_rn(a0.x * inv, a0.y * inv); o.x = *(uint32_t*)&h;
    h = __floats2half2_rn(a0.z * inv, a0.w * inv); o.y = *(uint32_t*)&h;
    mr[lane] = o;
    h = __floats2half2_rn(a1.x * inv, a1.y * inv); o.x = *(uint32_t*)&h;
    h = __floats2half2_rn(a1.z * inv, a1.w * inv); o.y = *(uint32_t*)&h;
    mr[lane + 32] = o;
    h = __floats2half2_rn(a2.x * inv, a2.y * inv); o.x = *(uint32_t*)&h;
    h = __floats2half2_rn(a2.z * inv, a2.w * inv); o.y = *(uint32_t*)&h;
    mr[lane + 64] = o;
}

// ---------------- fused GraphConv GEMM (fp16 m16n8k16, fp32 accum) ---------
// Od = relu(mean @ Wrel + A2 @ Wroot + brel)
// fp16 mantissa == tf32 mantissa -> no extra rounding error vs tf32 path.
// 128x128 CTA tile, BK=32, 8 warps, cp.async double buffer, 40KB static smem
// -> 2 CTAs/SM.
#define BM 128
#define BN 128
#define BK 32
#define PITCH 40                 // halves per smem row; word pattern g*20+t is
                                 // a permutation mod 32 -> conflict-free
#define TILEB (128 * PITCH * 2)  // 10240 bytes (A tile == B tile size)
#define BUFB  (2 * TILEB)        // 20480 bytes per buffer (A + B)

__global__ __launch_bounds__(256, 2) void k_layer_mma(
    const float* __restrict__ brel,
    float* __restrict__ yout, int layer)
{
    __shared__ char sm[2 * BUFB];   // 40960 bytes

    const __half* A2    = (layer == 1) ? g_xh : g_hh;
    const __half* Wrel  = g_Wh[(layer == 1) ? 0 : 2];   // [N][K] fp16
    const __half* Wroot = g_Wh[(layer == 1) ? 1 : 3];

    const int t = threadIdx.x;
    const int warp = t >> 5, lane = t & 31;
    const int warpM = warp >> 1, warpN = warp & 1;
    const int g = lane >> 2, t4 = lane & 3;
    const int rowBase = blockIdx.y * BM;
    const int colBase = blockIdx.x * BN;

    float acc[2][8][4];
#pragma unroll
    for (int mm = 0; mm < 2; mm++)
#pragma unroll
        for (int nn = 0; nn < 8; nn++)
#pragma unroll
            for (int q = 0; q < 4; q++) acc[mm][nn][q] = 0.f;

    // 24 K-iterations: it<12 -> (g_meanh, Wrel); it>=12 -> (A2, Wroot)
    auto stage = [&](int it, int buf) {
        const __half* A = (it < 12) ? g_meanh : A2;
        const __half* W = (it < 12) ? Wrel : Wroot;
        int k0 = (it < 12 ? it : it - 12) * BK;
        char* As = sm + buf * BUFB;
        char* Bs = As + TILEB;
#pragma unroll
        for (int i = 0; i < 2; i++) {
            int c = t + i * 256;          // 512 16B chunks each for A and B
            int r = c >> 2;               // tile row 0..127
            int o = (c & 3) * 8;          // half offset within row
            int boff = r * (PITCH * 2) + (c & 3) * 16;
            int grow = rowBase + r;
            cp16(As + boff, A + (size_t)grow * Dd + k0 + o, grow < Nn);
            cp16(Bs + boff, W + (size_t)(colBase + r) * Dd + k0 + o, true);
        }
    };

    auto compute = [&](int buf) {
        const uint32_t* As32 = (const uint32_t*)(sm + buf * BUFB);
        const uint32_t* Bs32 = (const uint32_t*)(sm + buf * BUFB + TILEB);
#pragma unroll
        for (int ks = 0; ks < 2; ks++) {           // two k16 steps per BK=32
            const int kw = ks * 8 + t4;            // b32 word offset in row
            uint32_t a[2][4], b[8][2];
#pragma unroll
            for (int mm = 0; mm < 2; mm++) {
                int r = warpM * 32 + mm * 16 + g;
                a[mm][0] = As32[r * (PITCH / 2) + kw];
                a[mm][1] = As32[(r + 8) * (PITCH / 2) + kw];
                a[mm][2] = As32[r * (PITCH / 2) + kw + 4];
                a[mm][3] = As32[(r + 8) * (PITCH / 2) + kw + 4];
            }
#pragma unroll
            for (int nn = 0; nn < 8; nn++) {
                int n = warpN * 64 + nn * 8 + g;
                b[nn][0] = Bs32[n * (PITCH / 2) + kw];
                b[nn][1] = Bs32[n * (PITCH / 2) + kw + 4];
            }
#pragma unroll
            for (int mm = 0; mm < 2; mm++)
#pragma unroll
                for (int nn = 0; nn < 8; nn++)
                    mma_f16(acc[mm][nn], a[mm], b[nn]);
        }
    };

    stage(0, 0); CP_COMMIT();
    stage(1, 1); CP_COMMIT();
    int buf = 0;
#pragma unroll 1
    for (int it = 0; it < 24; it++) {
        if (it < 23) { CP_WAIT(1); } else { CP_WAIT(0); }
        __syncthreads();
        compute(buf);
        __syncthreads();
        if (it + 2 < 24) { stage(it + 2, buf); CP_COMMIT(); }
        buf ^= 1;
    }

    // epilogue: bias + relu. layer1 -> g_hh (fp16); layer2 -> yout (fp32)
#pragma unroll
    for (int mm = 0; mm < 2; mm++) {
#pragma unroll
        for (int nn = 0; nn < 8; nn++) {
            int c = colBase + warpN * 64 + nn * 8 + t4 * 2;
            float b0 = brel[c], b1 = brel[c + 1];
            int r0 = rowBase + warpM * 32 + mm * 16 + g;
            int r1 = r0 + 8;
            float v00 = fmaxf(acc[mm][nn][0] + b0, 0.f);
            float v01 = fmaxf(acc[mm][nn][1] + b1, 0.f);
            float v10 = fmaxf(acc[mm][nn][2] + b0, 0.f);
            float v11 = fmaxf(acc[mm][nn][3] + b1, 0.f);
            if (layer == 1) {
                if (r0 < Nn) {
                    __half2 h = __floats2half2_rn(v00, v01);
                    *(__half2*)(g_hh + (size_t)r0 * Dd + c) = h;
                }
                if (r1 < Nn) {
                    __half2 h = __floats2half2_rn(v10, v11);
                    *(__half2*)(g_hh + (size_t)r1 * Dd + c) = h;
                }
            } else {
                if (r0 < Nn) *(float2*)(yout + (size_t)r0 * Dd + c) = make_float2(v00, v01);
                if (r1 < Nn) *(float2*)(yout + (size_t)r1 * Dd + c) = make_float2(v10, v11);
            }
        }
    }
}

// ---------------- final linear + sigmoid: warp per node ----------------
__global__ void k_final(const float* __restrict__ y,
                        const float* __restrict__ Wl,
                        const float* __restrict__ bl,
                        float* __restrict__ out)
{
    int gw = (blockIdx.x * blockDim.x + threadIdx.x) >> 5;
    int lane = threadIdx.x & 31;
    if (gw >= Nn) return;
    const float* yr = y + (size_t)gw * Dd;
    float s0 = 0.f, s1 = 0.f;
#pragma unroll
    for (int j = 0; j < 12; j++) {
        int k = lane + 32 * j;
        float v = yr[k];
        s0 += v * Wl[k * 2 + 0];
        s1 += v * Wl[k * 2 + 1];
    }
#pragma unroll
    for (int off = 16; off; off >>= 1) {
        s0 += __shfl_down_sync(0xffffffffu, s0, off);
        s1 += __shfl_down_sync(0xffffffffu, s1, off);
    }
    if (lane == 0) {
        out[gw * 2 + 0] = 1.f / (1.f + expf(-(s0 + bl[0])));
        out[gw * 2 + 1] = 1.f / (1.f + expf(-(s1 + bl[1])));
    }
}

// ---------------- launch ----------------
extern "C" void kernel_launch(void* const* d_in, const int* in_sizes, int n_in,
                              void* d_out, int out_size)
{
    const float* x   = (const float*)d_in[0];
    const void*  ei  = d_in[1];
    const float* ew  = (const float*)d_in[2];
    const float* br1 = (const float*)d_in[4];
    const float* br2 = (const float*)d_in[7];
    const float* Wl  = (const float*)d_in[9];
    const float* bl  = (const float*)d_in[10];

    float* out = (float*)d_out;                 // [N, 2]
    float* y   = out + (size_t)Nn * OUTC;       // [N, 384]

    dim3 gg(Dd / BN, (Nn + BM - 1) / BM);       // (3, 782)

    k_init<<<37500, 1024>>>((const int*)ei, x,
                            (const float*)d_in[3], (const float*)d_in[5],
                            (const float*)d_in[6], (const float*)d_in[8]);   // 1
    k_scan1<<<(Nn + 1023) / 1024, 1024>>>();                                  // 2
    k_scan23<<<(Nn + 255) / 256, 256>>>();                                    // 3
    k_fill<<<(Ee + 255) / 256, 256>>>(ei, ew);                                // 4
    k_agg<<<(Nn * 32 + 255) / 256, 256>>>(1);                                 // 5
    k_layer_mma<<<gg, 256>>>(br1, nullptr, 1);                                // 6
    k_agg<<<(Nn * 32 + 255) / 256, 256>>>(2);                                 // 7
    k_layer_mma<<<gg, 256>>>(br2, y, 2);                                      // 8
    k_final<<<(Nn * 32 + 255) / 256, 256>>>(y, Wl, bl, out);                  // 9
}

// round 6
// speedup vs baseline: 4.1262x; 1.0858x over previous
#include <cuda_runtime.h>
#include <cuda_fp16.h>
#include <cstdint>

#define Nn   100000
#define Ee   800000
#define Dd   384
#define OUTC 2

// ---------------- device scratch (no allocations allowed) ----------------
__device__ __half g_xh[(size_t)Nn * Dd];    // 76.8 MB  fp16 copy of x
__device__ __half g_meanh[(size_t)Nn * Dd]; // 76.8 MB  aggregated mean (fp16)
__device__ __half g_hh[(size_t)Nn * Dd];    // 76.8 MB  layer-1 output (fp16)
__device__ __half g_Wh[4][Dd * Dd];         // fp16 weights, TRANSPOSED [N][K]
__device__ int    g_deg[Nn];                // zero at load; re-zeroed by k_scan23
__device__ int    g_ptr[Nn + 1];
__device__ int    g_cursor[Nn];
__device__ int    g_col[Ee];
__device__ float  g_wt[Ee];
__device__ int    g_part[128];

// ---------------- helpers ----------------
__device__ __forceinline__ void cp16(void* smem, const void* g, bool pred) {
    uint32_t s = (uint32_t)__cvta_generic_to_shared(smem);
    int bytes = pred ? 16 : 0;
    asm volatile("cp.async.cg.shared.global [%0], [%1], 16, %2;\n"
                 :: "r"(s), "l"(g), "r"(bytes));
}
#define CP_COMMIT() asm volatile("cp.async.commit_group;\n" ::: "memory")
#define CP_WAIT(n)  asm volatile("cp.async.wait_group %0;\n" :: "n"(n) : "memory")

__device__ __forceinline__ void mma_f16(float* d, const uint32_t* a, const uint32_t* b) {
    asm volatile(
        "mma.sync.aligned.m16n8k16.row.col.f32.f16.f16.f32 "
        "{%0,%1,%2,%3}, {%4,%5,%6,%7}, {%8,%9}, {%0,%1,%2,%3};\n"
        : "+f"(d[0]), "+f"(d[1]), "+f"(d[2]), "+f"(d[3])
        : "r"(a[0]), "r"(a[1]), "r"(a[2]), "r"(a[3]), "r"(b[0]), "r"(b[1]));
}

// jnp.int64 may be canonicalized to int32 by JAX. If the data really is int64
// (LE, values < 2^32), every odd int32 word is 0. 16 random indices in
// [0,100000) all having zero high words is impossible.
__device__ __forceinline__ bool probe64(const int* __restrict__ ei) {
    bool is64 = true;
#pragma unroll
    for (int j = 1; j < 32; j += 2) is64 &= (ei[j] == 0);
    return is64;
}
__device__ __forceinline__ int edge_at(const void* ei, int pos, bool is64) {
    return is64 ? (int)((const long long*)ei)[pos] : ((const int*)ei)[pos];
}

// accumulate 8 fp16 (one uint4) into 8 fp32 with weight w
__device__ __forceinline__ void acc8(float* acc, uint4 u, float w) {
    float2 f;
    f = __half22float2(*(__half2*)&u.x); acc[0] += w * f.x; acc[1] += w * f.y;
    f = __half22float2(*(__half2*)&u.y); acc[2] += w * f.x; acc[3] += w * f.y;
    f = __half22float2(*(__half2*)&u.z); acc[4] += w * f.x; acc[5] += w * f.y;
    f = __half22float2(*(__half2*)&u.w); acc[6] += w * f.x; acc[7] += w * f.y;
}
__device__ __forceinline__ uint4 pack8(const float* a, float inv) {
    uint4 o; __half2 h;
    h = __floats2half2_rn(a[0] * inv, a[1] * inv); o.x = *(uint32_t*)&h;
    h = __floats2half2_rn(a[2] * inv, a[3] * inv); o.y = *(uint32_t*)&h;
    h = __floats2half2_rn(a[4] * inv, a[5] * inv); o.z = *(uint32_t*)&h;
    h = __floats2half2_rn(a[6] * inv, a[7] * inv); o.w = *(uint32_t*)&h;
    return o;
}

// ---------------- init: x->fp16, weights->fp16 transposed, degree count -----
// g_deg is zero at module load and re-zeroed by k_scan23 after each use.
__global__ void k_init(const int* __restrict__ ei,
                       const float* __restrict__ x,
                       const float* __restrict__ w0, const float* __restrict__ w1,
                       const float* __restrict__ w2, const float* __restrict__ w3) {
    size_t i = (size_t)blockIdx.x * blockDim.x + threadIdx.x;
    g_xh[i] = __float2half_rn(x[i]);
    if (i < Dd * Dd) {
        int k = (int)i / Dd, n = (int)i % Dd;
        int o = n * Dd + k;                 // transpose [K][N] -> [N][K]
        g_Wh[0][o] = __float2half_rn(w0[i]);
        g_Wh[1][o] = __float2half_rn(w1[i]);
        g_Wh[2][o] = __float2half_rn(w2[i]);
        g_Wh[3][o] = __float2half_rn(w3[i]);
    }
    if (i < Ee) {
        bool is64 = probe64(ei);
        atomicAdd(&g_deg[edge_at(ei, Ee + (int)i, is64)], 1);
    }
}

// ---------------- CSR scan ----------------
__global__ void k_scan1() {
    __shared__ int s[1024];
    int tid = threadIdx.x;
    int i = blockIdx.x * 1024 + tid;
    int v = (i < Nn) ? g_deg[i] : 0;
    s[tid] = v;
    __syncthreads();
    for (int off = 1; off < 1024; off <<= 1) {
        int t = (tid >= off) ? s[tid - off] : 0;
        __syncthreads();
        s[tid] += t;
        __syncthreads();
    }
    if (i < Nn) g_ptr[i] = s[tid];
    if (tid == 1023) g_part[blockIdx.x] = s[1023];
}
__global__ void k_scan23() {
    int i = blockIdx.x * blockDim.x + threadIdx.x;
    if (i < Nn) {
        int nb = i >> 10;
        int run = 0;
        for (int b = 0; b < nb; b++) run += g_part[b];
        int excl = g_ptr[i] - g_deg[i] + run;
        g_ptr[i] = excl;
        g_cursor[i] = excl;
        g_deg[i] = 0;                 // invariant: deg zeroed after consumption
    }
    if (i == 0) g_ptr[Nn] = Ee;
}
__global__ void k_fill(const void* __restrict__ ei, const float* __restrict__ ew) {
    int e = blockIdx.x * blockDim.x + threadIdx.x;
    if (e < Ee) {
        bool is64 = probe64((const int*)ei);
        int s = edge_at(ei, e, is64);
        int d = edge_at(ei, Ee + e, is64);
        int pos = atomicAdd(&g_cursor[d], 1);
        g_col[pos] = s;
        g_wt[pos] = ew[e];
    }
}

// ---------------- mean aggregation: warp per dst node, uint4 x2-unroll ------
// Row = 48 uint4 chunks. Lane l owns chunk l (all lanes) and chunk 32+l
// (lanes < 16). Edge loop unrolled x2 -> up to 6 independent LDG.128 in flight.
__global__ void k_agg(int layer) {
    int gw = (blockIdx.x * blockDim.x + threadIdx.x) >> 5;
    int lane = threadIdx.x & 31;
    if (gw >= Nn) return;
    const uint4* X = (const uint4*)(layer == 1 ? g_xh : g_hh);  // 48 per row
    int s = g_ptr[gw], eEnd = g_ptr[gw + 1];
    const bool lo = lane < 16;
    float accA[8] = {0.f, 0.f, 0.f, 0.f, 0.f, 0.f, 0.f, 0.f};
    float accB[8] = {0.f, 0.f, 0.f, 0.f, 0.f, 0.f, 0.f, 0.f};
    int e = s;
    for (; e + 1 < eEnd; e += 2) {
        int s0 = g_col[e], s1 = g_col[e + 1];
        float w0 = g_wt[e], w1 = g_wt[e + 1];
        const uint4* r0 = X + (size_t)s0 * 48;
        const uint4* r1 = X + (size_t)s1 * 48;
        uint4 a0 = __ldg(r0 + lane);
        uint4 a1 = __ldg(r1 + lane);
        uint4 b0, b1;
        if (lo) {
            b0 = __ldg(r0 + 32 + lane);
            b1 = __ldg(r1 + 32 + lane);
        }
        acc8(accA, a0, w0);
        acc8(accA, a1, w1);
        if (lo) {
            acc8(accB, b0, w0);
            acc8(accB, b1, w1);
        }
    }
    if (e < eEnd) {
        int s0 = g_col[e];
        float w0 = g_wt[e];
        const uint4* r0 = X + (size_t)s0 * 48;
        uint4 a0 = __ldg(r0 + lane);
        acc8(accA, a0, w0);
        if (lo) {
            uint4 b0 = __ldg(r0 + 32 + lane);
            acc8(accB, b0, w0);
        }
    }
    float inv = 1.f / fmaxf((float)(eEnd - s), 1.f);
    uint4* mr = (uint4*)(g_meanh + (size_t)gw * Dd);
    mr[lane] = pack8(accA, inv);
    if (lo) mr[32 + lane] = pack8(accB, inv);
}

// ---------------- fused GraphConv GEMM (fp16 m16n8k16, fp32 accum) ---------
// Od = relu(mean @ Wrel + A2 @ Wroot + brel)
// 128x128 CTA tile, BK=32, FOUR warps with 64x64 warp tiles (halved smem
// fragment traffic per FLOP vs 32x64), cp.async double buffer, 40KB smem,
// 2 CTAs/SM.
#define BM 128
#define BN 128
#define BK 32
#define PITCH 40                 // halves per smem row; conflict-free word perm
#define TILEB (128 * PITCH * 2)  // 10240 bytes per tile
#define BUFB  (2 * TILEB)        // A + B per buffer

__global__ __launch_bounds__(128, 2) void k_layer_mma(
    const float* __restrict__ brel,
    float* __restrict__ yout, int layer)
{
    __shared__ char sm[2 * BUFB];   // 40960 bytes

    const __half* A2    = (layer == 1) ? g_xh : g_hh;
    const __half* Wrel  = g_Wh[(layer == 1) ? 0 : 2];   // [N][K] fp16
    const __half* Wroot = g_Wh[(layer == 1) ? 1 : 3];

    const int t = threadIdx.x;
    const int warp = t >> 5, lane = t & 31;
    const int warpM = warp >> 1, warpN = warp & 1;       // 2x2 of 64x64 tiles
    const int g = lane >> 2, t4 = lane & 3;
    const int rowBase = blockIdx.y * BM;
    const int colBase = blockIdx.x * BN;

    float acc[4][8][4];
#pragma unroll
    for (int mm = 0; mm < 4; mm++)
#pragma unroll
        for (int nn = 0; nn < 8; nn++)
#pragma unroll
            for (int q = 0; q < 4; q++) acc[mm][nn][q] = 0.f;

    // 24 K-iterations: it<12 -> (g_meanh, Wrel); it>=12 -> (A2, Wroot)
    auto stage = [&](int it, int buf) {
        const __half* A = (it < 12) ? g_meanh : A2;
        const __half* W = (it < 12) ? Wrel : Wroot;
        int k0 = (it < 12 ? it : it - 12) * BK;
        char* As = sm + buf * BUFB;
        char* Bs = As + TILEB;
#pragma unroll
        for (int i = 0; i < 4; i++) {
            int c = t + i * 128;          // 512 16B chunks each for A and B
            int r = c >> 2;               // tile row 0..127
            int o = (c & 3) * 8;          // half offset within row
            int boff = r * (PITCH * 2) + (c & 3) * 16;
            int grow = rowBase + r;
            cp16(As + boff, A + (size_t)grow * Dd + k0 + o, grow < Nn);
            cp16(Bs + boff, W + (size_t)(colBase + r) * Dd + k0 + o, true);
        }
    };

    auto compute = [&](int buf) {
        const uint32_t* As32 = (const uint32_t*)(sm + buf * BUFB);
        const uint32_t* Bs32 = (const uint32_t*)(sm + buf * BUFB + TILEB);
#pragma unroll
        for (int ks = 0; ks < 2; ks++) {           // two k16 steps per BK=32
            const int kw = ks * 8 + t4;            // b32 word offset in row
            uint32_t a[4][4], b[8][2];
#pragma unroll
            for (int mm = 0; mm < 4; mm++) {
                int r = warpM * 64 + mm * 16 + g;
                a[mm][0] = As32[r * (PITCH / 2) + kw];
                a[mm][1] = As32[(r + 8) * (PITCH / 2) + kw];
                a[mm][2] = As32[r * (PITCH / 2) + kw + 4];
                a[mm][3] = As32[(r + 8) * (PITCH / 2) + kw + 4];
            }
#pragma unroll
            for (int nn = 0; nn < 8; nn++) {
                int n = warpN * 64 + nn * 8 + g;
                b[nn][0] = Bs32[n * (PITCH / 2) + kw];
                b[nn][1] = Bs32[n * (PITCH / 2) + kw + 4];
            }
#pragma unroll
            for (int mm = 0; mm < 4; mm++)
#pragma unroll
                for (int nn = 0; nn < 8; nn++)
                    mma_f16(acc[mm][nn], a[mm], b[nn]);
        }
    };

    stage(0, 0); CP_COMMIT();
    stage(1, 1); CP_COMMIT();
    int buf = 0;
#pragma unroll 1
    for (int it = 0; it < 24; it++) {
        if (it < 23) { CP_WAIT(1); } else { CP_WAIT(0); }
        __syncthreads();
        compute(buf);
        __syncthreads();
        if (it + 2 < 24) { stage(it + 2, buf); CP_COMMIT(); }
        buf ^= 1;
    }

    // epilogue: bias + relu. layer1 -> g_hh (fp16); layer2 -> yout (fp32)
#pragma unroll
    for (int mm = 0; mm < 4; mm++) {
#pragma unroll
        for (int nn = 0; nn < 8; nn++) {
            int c = colBase + warpN * 64 + nn * 8 + t4 * 2;
            float b0 = brel[c], b1 = brel[c + 1];
            int r0 = rowBase + warpM * 64 + mm * 16 + g;
            int r1 = r0 + 8;
            float v00 = fmaxf(acc[mm][nn][0] + b0, 0.f);
            float v01 = fmaxf(acc[mm][nn][1] + b1, 0.f);
            float v10 = fmaxf(acc[mm][nn][2] + b0, 0.f);
            float v11 = fmaxf(acc[mm][nn][3] + b1, 0.f);
            if (layer == 1) {
                if (r0 < Nn) {
                    __half2 h = __floats2half2_rn(v00, v01);
                    *(__half2*)(g_hh + (size_t)r0 * Dd + c) = h;
                }
                if (r1 < Nn) {
                    __half2 h = __floats2half2_rn(v10, v11);
                    *(__half2*)(g_hh + (size_t)r1 * Dd + c) = h;
                }
            } else {
                if (r0 < Nn) *(float2*)(yout + (size_t)r0 * Dd + c) = make_float2(v00, v01);
                if (r1 < Nn) *(float2*)(yout + (size_t)r1 * Dd + c) = make_float2(v10, v11);
            }
        }
    }
}

// ---------------- final linear + sigmoid: warp per node ----------------
__global__ void k_final(const float* __restrict__ y,
                        const float* __restrict__ Wl,
                        const float* __restrict__ bl,
                        float* __restrict__ out)
{
    int gw = (blockIdx.x * blockDim.x + threadIdx.x) >> 5;
    int lane = threadIdx.x & 31;
    if (gw >= Nn) return;
    const float* yr = y + (size_t)gw * Dd;
    float s0 = 0.f, s1 = 0.f;
#pragma unroll
    for (int j = 0; j < 12; j++) {
        int k = lane + 32 * j;
        float v = yr[k];
        s0 += v * Wl[k * 2 + 0];
        s1 += v * Wl[k * 2 + 1];
    }
#pragma unroll
    for (int off = 16; off; off >>= 1) {
        s0 += __shfl_down_sync(0xffffffffu, s0, off);
        s1 += __shfl_down_sync(0xffffffffu, s1, off);
    }
    if (lane == 0) {
        out[gw * 2 + 0] = 1.f / (1.f + expf(-(s0 + bl[0])));
        out[gw * 2 + 1] = 1.f / (1.f + expf(-(s1 + bl[1])));
    }
}

// ---------------- launch ----------------
extern "C" void kernel_launch(void* const* d_in, const int* in_sizes, int n_in,
                              void* d_out, int out_size)
{
    const float* x   = (const float*)d_in[0];
    const void*  ei  = d_in[1];
    const float* ew  = (const float*)d_in[2];
    const float* br1 = (const float*)d_in[4];
    const float* br2 = (const float*)d_in[7];
    const float* Wl  = (const float*)d_in[9];
    const float* bl  = (const float*)d_in[10];

    float* out = (float*)d_out;                 // [N, 2]
    float* y   = out + (size_t)Nn * OUTC;       // [N, 384]

    dim3 gg(Dd / BN, (Nn + BM - 1) / BM);       // (3, 782)

    k_init<<<37500, 1024>>>((const int*)ei, x,
                            (const float*)d_in[3], (const float*)d_in[5],
                            (const float*)d_in[6], (const float*)d_in[8]);   // 1
    k_scan1<<<(Nn + 1023) / 1024, 1024>>>();                                  // 2
    k_scan23<<<(Nn + 255) / 256, 256>>>();                                    // 3
    k_fill<<<(Ee + 255) / 256, 256>>>(ei, ew);                                // 4
    k_agg<<<(Nn * 32 + 255) / 256, 256>>>(1);                                 // 5
    k_layer_mma<<<gg, 128>>>(br1, nullptr, 1);                                // 6
    k_agg<<<(Nn * 32 + 255) / 256, 256>>>(2);                                 // 7
    k_layer_mma<<<gg, 128>>>(br2, y, 2);                                      // 8
    k_final<<<(Nn * 32 + 255) / 256, 256>>>(y, Wl, bl, out);                  // 9
}